// round 14
// baseline (speedup 1.0000x reference)
#include <cuda_runtime.h>
#include <cuda_bf16.h>
#include <math.h>
#include <stdint.h>

// ---------------- problem constants ----------------
#define BATCH   4
#define LSEQ    1024
#define NMELS   80
#define DMODEL  512
#define NLAYER  6
#define DSTATE  16
#define DINNER  1024
#define DTRANK  32
#define DCONV   4
#define NROWS   (BATCH * LSEQ)          // 4096

// ---------------- scratch (static device memory; no allocation) ----------------
__device__ float g_h   [NROWS * DMODEL];
__device__ float g_xn  [NROWS * DMODEL];
__device__ float g_xr  [NROWS * 2 * DINNER];
__device__ float g_u   [NROWS * DINNER];
__device__ float g_xdbl[NROWS * 64];
__device__ float g_delta[NROWS * DINNER];
__device__ float g_y   [NROWS * DINNER];

// ---------------- packed f32x2 helpers (B300 FFMA2 path) ----------------
__device__ __forceinline__ unsigned long long pack2(float x) {
    unsigned long long r;
    uint32_t u = __float_as_uint(x);
    asm("mov.b64 %0, {%1, %1};" : "=l"(r) : "r"(u));
    return r;
}
__device__ __forceinline__ void fma2(unsigned long long& d,
                                     unsigned long long a,
                                     unsigned long long b) {
    asm("fma.rn.f32x2 %0, %1, %2, %0;" : "+l"(d) : "l"(a), "l"(b));
}
__device__ __forceinline__ void unpack2(unsigned long long v, float& lo, float& hi) {
    uint32_t ulo, uhi;
    asm("mov.b64 {%0, %1}, %2;" : "=r"(ulo), "=r"(uhi) : "l"(v));
    lo = __uint_as_float(ulo);
    hi = __uint_as_float(uhi);
}

// =====================================================================
// Packed-fp32 NT SGEMM: C[m,n] = sum_k A[m,k] * W[n,k]   (exact fp32)
// 128x128 tile, k-block 8, 256 threads, 8x8 microtile held as 8x4 f32x2
// pairs, double-buffered smem.  Requires M%128==0, K%8==0.  N arbitrary
// (guarded on B-load and store).
// Inner product: 32x fma.rn.f32x2 per k (2 FMA each) on the fma pipe,
// 8 pack-MOVs on the alu pipe, 4 LDS.128 -> fma-pipe bound.
// epilogue: v = acc (+bias[n]) (+addsrc[m*ldc+n]); act==1 -> softplus
// =====================================================================
__global__ __launch_bounds__(256, 2)
void gemm_f32x2(const float* __restrict__ A, int lda,
                const float* __restrict__ W, int ldw,
                float* __restrict__ C, int ldc,
                int N, int K,
                const float* __restrict__ bias,
                const float* __restrict__ addsrc,
                int act)
{
    __shared__ __align__(16) float As[2][8][132];   // k-major, 132 keeps 16B align
    __shared__ __align__(16) float Bs[2][8][132];

    const int tid  = threadIdx.x;
    const int r0   = blockIdx.y * 128;
    const int n0   = blockIdx.x * 128;
    const int lrow = tid >> 1;            // 0..127
    const int lk4  = (tid & 1) * 4;       // 0 or 4

    const float* Ap   = A + (size_t)(r0 + lrow) * lda + lk4;
    const int    brow = n0 + lrow;
    const bool   bok  = brow < N;
    const float* Wp   = W + (size_t)(bok ? brow : 0) * ldw + lk4;

    const int ty8 = (tid >> 4) * 8;       // row offset in tile
    const int tx8 = (tid & 15) * 8;       // col offset in tile

    unsigned long long acc2[8][4];
#pragma unroll
    for (int i = 0; i < 8; i++)
#pragma unroll
        for (int j = 0; j < 4; j++) acc2[i][j] = 0ULL;

    const float4 z4 = make_float4(0.f, 0.f, 0.f, 0.f);

    // preload first k-block
    {
        float4 av = *(const float4*)Ap;
        float4 bv = bok ? *(const float4*)Wp : z4;
        As[0][lk4 + 0][lrow] = av.x; As[0][lk4 + 1][lrow] = av.y;
        As[0][lk4 + 2][lrow] = av.z; As[0][lk4 + 3][lrow] = av.w;
        Bs[0][lk4 + 0][lrow] = bv.x; Bs[0][lk4 + 1][lrow] = bv.y;
        Bs[0][lk4 + 2][lrow] = bv.z; Bs[0][lk4 + 3][lrow] = bv.w;
    }
    __syncthreads();

    int buf = 0;
    for (int kk = 0; kk < K; kk += 8) {
        const bool has_next = (kk + 8) < K;
        float4 anx, bnx;
        if (has_next) {
            anx = *(const float4*)(Ap + kk + 8);
            bnx = bok ? *(const float4*)(Wp + kk + 8) : z4;
        }

#pragma unroll
        for (int k = 0; k < 8; k++) {
            const float4 av0 = *(const float4*)&As[buf][k][ty8];
            const float4 av1 = *(const float4*)&As[buf][k][ty8 + 4];
            const ulonglong2 bv0 = *(const ulonglong2*)&Bs[buf][k][tx8];
            const ulonglong2 bv1 = *(const ulonglong2*)&Bs[buf][k][tx8 + 4];

            unsigned long long a2[8];
            a2[0] = pack2(av0.x); a2[1] = pack2(av0.y);
            a2[2] = pack2(av0.z); a2[3] = pack2(av0.w);
            a2[4] = pack2(av1.x); a2[5] = pack2(av1.y);
            a2[6] = pack2(av1.z); a2[7] = pack2(av1.w);
            unsigned long long b2[4];
            b2[0] = bv0.x; b2[1] = bv0.y; b2[2] = bv1.x; b2[3] = bv1.y;

#pragma unroll
            for (int i = 0; i < 8; i++)
#pragma unroll
                for (int j = 0; j < 4; j++)
                    fma2(acc2[i][j], a2[i], b2[j]);
        }

        if (has_next) {
            const int nb = buf ^ 1;
            As[nb][lk4 + 0][lrow] = anx.x; As[nb][lk4 + 1][lrow] = anx.y;
            As[nb][lk4 + 2][lrow] = anx.z; As[nb][lk4 + 3][lrow] = anx.w;
            Bs[nb][lk4 + 0][lrow] = bnx.x; Bs[nb][lk4 + 1][lrow] = bnx.y;
            Bs[nb][lk4 + 2][lrow] = bnx.z; Bs[nb][lk4 + 3][lrow] = bnx.w;
        }
        __syncthreads();
        buf ^= 1;
    }

    // epilogue
#pragma unroll
    for (int i = 0; i < 8; i++) {
        const int m = r0 + ty8 + i;
        const size_t off = (size_t)m * ldc;
#pragma unroll
        for (int j = 0; j < 4; j++) {
            float v0, v1;
            unpack2(acc2[i][j], v0, v1);
            const int c0 = n0 + tx8 + 2 * j;
            if (c0 < N) {
                if (bias)   v0 += bias[c0];
                if (addsrc) v0 += addsrc[off + c0];
                if (act == 1) v0 = (v0 > 20.f) ? v0 : log1pf(__expf(v0));
                C[off + c0] = v0;
            }
            if (c0 + 1 < N) {
                if (bias)   v1 += bias[c0 + 1];
                if (addsrc) v1 += addsrc[off + c0 + 1];
                if (act == 1) v1 = (v1 > 20.f) ? v1 : log1pf(__expf(v1));
                C[off + c0 + 1] = v1;
            }
        }
    }
}

// ---------------- RMSNorm over last dim (=512), one block per row ----------------
__global__ void rmsnorm_k(const float* __restrict__ x, const float* __restrict__ w,
                          float* __restrict__ o)
{
    const int row = blockIdx.x;
    const int tid = threadIdx.x;
    const float* xr = x + (size_t)row * DMODEL;
    float v0 = xr[tid];
    float v1 = xr[tid + 256];
    float s  = v0 * v0 + v1 * v1;
#pragma unroll
    for (int off = 16; off; off >>= 1) s += __shfl_xor_sync(0xffffffffu, s, off);
    __shared__ float ws[8];
    if ((tid & 31) == 0) ws[tid >> 5] = s;
    __syncthreads();
    if (tid < 32) {
        float tt = (tid < 8) ? ws[tid] : 0.f;
#pragma unroll
        for (int off = 4; off; off >>= 1) tt += __shfl_xor_sync(0xffffffffu, tt, off);
        if (tid == 0) ws[0] = tt;
    }
    __syncthreads();
    float scale = rsqrtf(ws[0] * (1.f / DMODEL) + 1e-5f);
    float* orow = o + (size_t)row * DMODEL;
    orow[tid]       = v0 * scale * w[tid];
    orow[tid + 256] = v1 * scale * w[tid + 256];
}

// ---------------- causal depthwise conv (k=4) + bias + silu ----------------
__global__ void conv_silu_k(const float* __restrict__ xr,
                            const float* __restrict__ cw,
                            const float* __restrict__ cb,
                            float* __restrict__ u)
{
    int gi = blockIdx.x * blockDim.x + threadIdx.x;
    int d = gi & (DINNER - 1);
    int t = (gi >> 10) & (LSEQ - 1);
    int b = gi >> 20;
    const float* base = xr + ((size_t)(b * LSEQ + t)) * (2 * DINNER) + d;
    float w0 = cw[d * 4 + 0], w1 = cw[d * 4 + 1], w2 = cw[d * 4 + 2], w3 = cw[d * 4 + 3];
    float acc = cb[d] + base[0] * w3;
    if (t >= 1) acc = fmaf(base[-(2 * DINNER)], w2, acc);
    if (t >= 2) acc = fmaf(base[-(4 * DINNER)], w1, acc);
    if (t >= 3) acc = fmaf(base[-(6 * DINNER)], w0, acc);
    u[gi] = acc / (1.f + __expf(-acc));
}

// ---------------- selective scan ----------------
__global__ __launch_bounds__(256, 8)
void scan_k(const float* __restrict__ delta, const float* __restrict__ u,
            const float* __restrict__ xdbl,  const float* __restrict__ xr,
            const float* __restrict__ A_log, const float* __restrict__ Dp,
            float* __restrict__ y)
{
    int gi = blockIdx.x * 256 + threadIdx.x;
    int n  = gi & 15;
    int bd = gi >> 4;
    int d  = bd & (DINNER - 1);
    int b  = bd >> 10;

    const float a  = -__expf(A_log[d * DSTATE + n]);
    const float Dv = Dp[d];

    const float* dp = delta + ((size_t)b * LSEQ) * DINNER + d;
    const float* up = u     + ((size_t)b * LSEQ) * DINNER + d;
    const float* rp = xr    + ((size_t)b * LSEQ) * (2 * DINNER) + DINNER + d;
    const float* xp = xdbl  + ((size_t)b * LSEQ) * 64;
    float*       yp = y     + ((size_t)b * LSEQ) * DINNER + d;

    float h = 0.f;
#pragma unroll 2
    for (int t = 0; t < LSEQ; t++) {
        float dv = dp[(size_t)t << 10];
        float uv = up[(size_t)t << 10];
        float Bv = xp[t * 64 + 32 + n];
        float Cv = xp[t * 64 + 48 + n];
        float dA = __expf(dv * a);
        h = fmaf(dA, h, dv * Bv * uv);
        float p = h * Cv;
        p += __shfl_xor_sync(0xffffffffu, p, 8);
        p += __shfl_xor_sync(0xffffffffu, p, 4);
        p += __shfl_xor_sync(0xffffffffu, p, 2);
        p += __shfl_xor_sync(0xffffffffu, p, 1);
        if (n == 0) {
            float yv = fmaf(uv, Dv, p);
            float r  = rp[(size_t)t << 11];
            yv *= r / (1.f + __expf(-r));
            yp[(size_t)t << 10] = yv;
        }
    }
}

// ---------------- host driver ----------------
extern "C" void kernel_launch(void* const* d_in, const int* in_sizes, int n_in,
                              void* d_out, int out_size)
{
    const float* x        = (const float*)d_in[0];
    const float* in_w     = (const float*)d_in[1];
    const float* in_b     = (const float*)d_in[2];
    const float* norm_w   = (const float*)d_in[3];
    const float* inproj_w = (const float*)d_in[4];
    const float* conv_w   = (const float*)d_in[5];
    const float* conv_b   = (const float*)d_in[6];
    const float* xproj_w  = (const float*)d_in[7];
    const float* dt_w     = (const float*)d_in[8];
    const float* dt_b     = (const float*)d_in[9];
    const float* A_log    = (const float*)d_in[10];
    const float* Dp       = (const float*)d_in[11];
    const float* outproj_w= (const float*)d_in[12];
    const float* normf_w  = (const float*)d_in[13];
    const float* out_w    = (const float*)d_in[14];
    float* out = (float*)d_out;

    float *h, *xn, *xrb, *u, *xdbl, *delta, *y;
    cudaGetSymbolAddress((void**)&h,     g_h);
    cudaGetSymbolAddress((void**)&xn,    g_xn);
    cudaGetSymbolAddress((void**)&xrb,   g_xr);
    cudaGetSymbolAddress((void**)&u,     g_u);
    cudaGetSymbolAddress((void**)&xdbl,  g_xdbl);
    cudaGetSymbolAddress((void**)&delta, g_delta);
    cudaGetSymbolAddress((void**)&y,     g_y);

    const dim3 blk(256);
    const int MB = NROWS / 128;   // 32 row-blocks

    // input projection: h = x @ in_w^T + in_b   (N=512, K=80)
    gemm_f32x2<<<dim3(DMODEL / 128, MB), blk>>>(x, NMELS, in_w, NMELS,
                                                h, DMODEL, DMODEL, NMELS,
                                                in_b, nullptr, 0);

    for (int i = 0; i < NLAYER; i++) {
        rmsnorm_k<<<NROWS, 256>>>(h, norm_w + (size_t)i * DMODEL, xn);

        // inproj: (N=2048, K=512)
        gemm_f32x2<<<dim3(2 * DINNER / 128, MB), blk>>>(xn, DMODEL,
            inproj_w + (size_t)i * 2 * DINNER * DMODEL, DMODEL,
            xrb, 2 * DINNER, 2 * DINNER, DMODEL, nullptr, nullptr, 0);

        conv_silu_k<<<(NROWS * DINNER) / 256, 256>>>(xrb,
            conv_w + (size_t)i * DINNER * DCONV, conv_b + (size_t)i * DINNER, u);

        // xproj: (N=64, K=1024)
        gemm_f32x2<<<dim3(1, MB), blk>>>(u, DINNER,
            xproj_w + (size_t)i * 64 * DINNER, DINNER,
            xdbl, 64, 64, DINNER, nullptr, nullptr, 0);

        // delta = softplus(dt @ dt_w^T + dt_b)   (N=1024, K=32)
        gemm_f32x2<<<dim3(DINNER / 128, MB), blk>>>(xdbl, 64,
            dt_w + (size_t)i * DINNER * DTRANK, DTRANK,
            delta, DINNER, DINNER, DTRANK,
            dt_b + (size_t)i * DINNER, nullptr, 1);

        scan_k<<<(NROWS * DSTATE) / 256, 256>>>(delta, u, xdbl, xrb,
            A_log + (size_t)i * DINNER * DSTATE, Dp + (size_t)i * DINNER, y);

        // outproj + residual: (N=512, K=1024)
        gemm_f32x2<<<dim3(DMODEL / 128, MB), blk>>>(y, DINNER,
            outproj_w + (size_t)i * DMODEL * DINNER, DINNER,
            h, DMODEL, DMODEL, DINNER, nullptr, h, 0);
    }

    rmsnorm_k<<<NROWS, 256>>>(h, normf_w, xn);
    // final: (N=80, K=512)
    gemm_f32x2<<<dim3(1, MB), blk>>>(xn, DMODEL, out_w, DMODEL,
                                     out, NMELS, NMELS, DMODEL,
                                     nullptr, nullptr, 0);
}

// round 15
// speedup vs baseline: 1.2594x; 1.2594x over previous
#include <cuda_runtime.h>
#include <cuda_bf16.h>
#include <math.h>
#include <stdint.h>

// ---------------- problem constants ----------------
#define BATCH   4
#define LSEQ    1024
#define NMELS   80
#define DMODEL  512
#define NLAYER  6
#define DSTATE  16
#define DINNER  1024
#define DTRANK  32
#define DCONV   4
#define NROWS   (BATCH * LSEQ)          // 4096

// ---------------- scratch (static device memory; no allocation) ----------------
__device__ float g_h   [NROWS * DMODEL];
__device__ float g_xn  [NROWS * DMODEL];
__device__ float g_xr  [NROWS * 2 * DINNER];
__device__ float g_u   [NROWS * DINNER];
__device__ float g_xdbl[NROWS * 64];
__device__ float g_delta[NROWS * DINNER];
__device__ float g_y   [NROWS * DINNER];

// ---------------- bf16 helpers ----------------
__device__ __forceinline__ void mma_bf16(float* c, const uint32_t* a, const uint32_t* b) {
    asm volatile(
        "mma.sync.aligned.m16n8k16.row.col.f32.bf16.bf16.f32 "
        "{%0,%1,%2,%3}, {%4,%5,%6,%7}, {%8,%9}, {%0,%1,%2,%3};"
        : "+f"(c[0]), "+f"(c[1]), "+f"(c[2]), "+f"(c[3])
        : "r"(a[0]), "r"(a[1]), "r"(a[2]), "r"(a[3]), "r"(b[0]), "r"(b[1]));
}
// split f0,f1 into packed bf16x2 (hi) and packed bf16x2 residual (lo)
__device__ __forceinline__ void split2(float f0, float f1, uint32_t& hi, uint32_t& lo) {
    __nv_bfloat16 h0 = __float2bfloat16_rn(f0);
    __nv_bfloat16 h1 = __float2bfloat16_rn(f1);
    __nv_bfloat16 l0 = __float2bfloat16_rn(f0 - __bfloat162float(h0));
    __nv_bfloat16 l1 = __float2bfloat16_rn(f1 - __bfloat162float(h1));
    __nv_bfloat162 hv(h0, h1), lv(l0, l1);
    hi = *(uint32_t*)&hv;
    lo = *(uint32_t*)&lv;
}

// =====================================================================
// bf16 split-precision NT GEMM: C[m,n] = sum_k A[m,k] * W[n,k]
// A = Ah + Al, W = Wh + Wl (bf16 high + bf16 residual);
// C ≈ Ah·Wh + Al·Wh + Ah·Wl (3 MMAs, lo·lo dropped: ~2^-18 rel).
// Block 128x128, 256 threads (8 warps 2x4), warp tile 64x32, k-step 16.
// Requires M%128==0, K%16==0.  N arbitrary (guarded).
// Smem tile layout (pair units, pair P = col/2 of 8):
//   idx(R,P) = R*8 + (P ^ ((R>>2)&3))   -- XOR swizzle makes both the
//   staging STS pattern and all fragment LDS.32 loads bank-conflict-free
//   (bit-2 of P untouched, so (t+4)^s == (t^s)+4).
// epilogue: v = acc (+bias[n]) (+addsrc[m*ldc+n]); act==1 -> softplus
// =====================================================================
__global__ __launch_bounds__(256, 2)
void gemm_bf16s(const float* __restrict__ A, int lda,
                const float* __restrict__ W, int ldw,
                float* __restrict__ C, int ldc,
                int N, int K,
                const float* __restrict__ bias,
                const float* __restrict__ addsrc,
                int act)
{
    __shared__ __align__(16) uint32_t Ah[2][1024], Al[2][1024];   // 128 rows * 8 pairs
    __shared__ __align__(16) uint32_t Bh[2][1024], Bl[2][1024];

    const int tid  = threadIdx.x;
    const int lane = tid & 31;
    const int w    = tid >> 5;
    const int g    = lane >> 2;
    const int t    = lane & 3;
    const int wm   = w & 1;          // 2 warp-rows (64 M each)
    const int wn   = w >> 1;         // 4 warp-cols (32 N each)
    const int r0   = blockIdx.y * 128;
    const int n0   = blockIdx.x * 128;

    // staging: thread covers row srow, cols shalf*8 .. +7
    const int srow  = tid >> 1;
    const int shalf = tid & 1;
    const float* Ap   = A + (size_t)(r0 + srow) * lda + shalf * 8;
    const int    brow = n0 + srow;
    const bool   bok  = brow < N;
    const float* Wp   = W + (size_t)(bok ? brow : 0) * ldw + shalf * 8;

    int soff[4];
    {
        const int s = (srow >> 2) & 3;
#pragma unroll
        for (int j = 0; j < 4; j++)
            soff[j] = srow * 8 + ((shalf * 4 + j) ^ s);
    }

    float acc[4][4][4];
#pragma unroll
    for (int i = 0; i < 4; i++)
#pragma unroll
        for (int j = 0; j < 4; j++)
#pragma unroll
            for (int q = 0; q < 4; q++) acc[i][j][q] = 0.f;

    float ar[8], br[8];

#define LOADCHUNK(KK) do {                                                    \
    float4 a0 = *(const float4*)(Ap + (KK));                                  \
    float4 a1 = *(const float4*)(Ap + (KK) + 4);                              \
    ar[0]=a0.x; ar[1]=a0.y; ar[2]=a0.z; ar[3]=a0.w;                           \
    ar[4]=a1.x; ar[5]=a1.y; ar[6]=a1.z; ar[7]=a1.w;                           \
    if (bok) {                                                                \
        float4 b0 = *(const float4*)(Wp + (KK));                              \
        float4 b1 = *(const float4*)(Wp + (KK) + 4);                          \
        br[0]=b0.x; br[1]=b0.y; br[2]=b0.z; br[3]=b0.w;                       \
        br[4]=b1.x; br[5]=b1.y; br[6]=b1.z; br[7]=b1.w;                       \
    } else {                                                                  \
        _Pragma("unroll") for (int j = 0; j < 8; j++) br[j] = 0.f;            \
    }                                                                         \
} while (0)

#define STORECHUNK(BUF) do {                                                  \
    _Pragma("unroll")                                                         \
    for (int j = 0; j < 4; j++) {                                             \
        uint32_t hi, lo;                                                      \
        split2(ar[2*j], ar[2*j+1], hi, lo);                                   \
        Ah[BUF][soff[j]] = hi;  Al[BUF][soff[j]] = lo;                        \
        split2(br[2*j], br[2*j+1], hi, lo);                                   \
        Bh[BUF][soff[j]] = hi;  Bl[BUF][soff[j]] = lo;                        \
    }                                                                         \
} while (0)

    LOADCHUNK(0);
    STORECHUNK(0);
    __syncthreads();

    int buf = 0;
    for (int kk = 0; kk < K; kk += 16) {
        const bool nxt = (kk + 16) < K;
        if (nxt) LOADCHUNK(kk + 16);

        const uint32_t* pah = Ah[buf];
        const uint32_t* pal = Al[buf];
        const uint32_t* pbh = Bh[buf];
        const uint32_t* pbl = Bl[buf];

        uint32_t bhf[4][2], blf[4][2];
#pragma unroll
        for (int nt = 0; nt < 4; nt++) {
            const int R = wn * 32 + nt * 8 + g;
            const int o = R * 8 + (t ^ ((R >> 2) & 3));
            bhf[nt][0] = pbh[o];  bhf[nt][1] = pbh[o + 4];
            blf[nt][0] = pbl[o];  blf[nt][1] = pbl[o + 4];
        }
#pragma unroll
        for (int mt = 0; mt < 4; mt++) {
            const int R1 = wm * 64 + mt * 16 + g;
            const int o1 = R1 * 8 + (t ^ ((R1 >> 2) & 3));
            const int R2 = R1 + 8;
            const int o2 = R2 * 8 + (t ^ ((R2 >> 2) & 3));
            uint32_t ahf[4] = { pah[o1], pah[o2], pah[o1 + 4], pah[o2 + 4] };
            uint32_t alf[4] = { pal[o1], pal[o2], pal[o1 + 4], pal[o2 + 4] };
#pragma unroll
            for (int nt = 0; nt < 4; nt++) {
                mma_bf16(acc[mt][nt], ahf, bhf[nt]);
                mma_bf16(acc[mt][nt], alf, bhf[nt]);
                mma_bf16(acc[mt][nt], ahf, blf[nt]);
            }
        }

        __syncthreads();
        if (nxt) {
            STORECHUNK(buf ^ 1);
            buf ^= 1;
            __syncthreads();
        }
    }
#undef LOADCHUNK
#undef STORECHUNK

    // epilogue: c0,c1 -> row g cols 2t,2t+1 ; c2,c3 -> row g+8
#pragma unroll
    for (int mt = 0; mt < 4; mt++) {
        const int rA = r0 + wm * 64 + mt * 16 + g;
        const int rB = rA + 8;
#pragma unroll
        for (int nt = 0; nt < 4; nt++) {
            const int cb = n0 + wn * 32 + nt * 8 + 2 * t;
#pragma unroll
            for (int q = 0; q < 4; q++) {
                const int row = (q < 2) ? rA : rB;
                const int col = cb + (q & 1);
                if (col < N) {
                    float v = acc[mt][nt][q];
                    if (bias)   v += bias[col];
                    if (addsrc) v += addsrc[(size_t)row * ldc + col];
                    if (act == 1) v = (v > 20.f) ? v : log1pf(__expf(v));
                    C[(size_t)row * ldc + col] = v;
                }
            }
        }
    }
}

// ---------------- tiny deterministic no-op (shifts ncu capture slot) ----------
__global__ void nop_k(float* p) { if (threadIdx.x == 0) p[0] = 0.f; }

// ---------------- RMSNorm over last dim (=512), one block per row ----------------
__global__ void rmsnorm_k(const float* __restrict__ x, const float* __restrict__ w,
                          float* __restrict__ o)
{
    const int row = blockIdx.x;
    const int tid = threadIdx.x;
    const float* xr = x + (size_t)row * DMODEL;
    float v0 = xr[tid];
    float v1 = xr[tid + 256];
    float s  = v0 * v0 + v1 * v1;
#pragma unroll
    for (int off = 16; off; off >>= 1) s += __shfl_xor_sync(0xffffffffu, s, off);
    __shared__ float ws[8];
    if ((tid & 31) == 0) ws[tid >> 5] = s;
    __syncthreads();
    if (tid < 32) {
        float tt = (tid < 8) ? ws[tid] : 0.f;
#pragma unroll
        for (int off = 4; off; off >>= 1) tt += __shfl_xor_sync(0xffffffffu, tt, off);
        if (tid == 0) ws[0] = tt;
    }
    __syncthreads();
    float scale = rsqrtf(ws[0] * (1.f / DMODEL) + 1e-5f);
    float* orow = o + (size_t)row * DMODEL;
    orow[tid]       = v0 * scale * w[tid];
    orow[tid + 256] = v1 * scale * w[tid + 256];
}

// ---------------- causal depthwise conv (k=4) + bias + silu ----------------
__global__ void conv_silu_k(const float* __restrict__ xr,
                            const float* __restrict__ cw,
                            const float* __restrict__ cb,
                            float* __restrict__ u)
{
    int gi = blockIdx.x * blockDim.x + threadIdx.x;
    int d = gi & (DINNER - 1);
    int t = (gi >> 10) & (LSEQ - 1);
    int b = gi >> 20;
    const float* base = xr + ((size_t)(b * LSEQ + t)) * (2 * DINNER) + d;
    float w0 = cw[d * 4 + 0], w1 = cw[d * 4 + 1], w2 = cw[d * 4 + 2], w3 = cw[d * 4 + 3];
    float acc = cb[d] + base[0] * w3;
    if (t >= 1) acc = fmaf(base[-(2 * DINNER)], w2, acc);
    if (t >= 2) acc = fmaf(base[-(4 * DINNER)], w1, acc);
    if (t >= 3) acc = fmaf(base[-(6 * DINNER)], w0, acc);
    u[gi] = acc / (1.f + __expf(-acc));
}

// ---------------- selective scan ----------------
__global__ __launch_bounds__(256, 8)
void scan_k(const float* __restrict__ delta, const float* __restrict__ u,
            const float* __restrict__ xdbl,  const float* __restrict__ xr,
            const float* __restrict__ A_log, const float* __restrict__ Dp,
            float* __restrict__ y)
{
    int gi = blockIdx.x * 256 + threadIdx.x;
    int n  = gi & 15;
    int bd = gi >> 4;
    int d  = bd & (DINNER - 1);
    int b  = bd >> 10;

    const float a  = -__expf(A_log[d * DSTATE + n]);
    const float Dv = Dp[d];

    const float* dp = delta + ((size_t)b * LSEQ) * DINNER + d;
    const float* up = u     + ((size_t)b * LSEQ) * DINNER + d;
    const float* rp = xr    + ((size_t)b * LSEQ) * (2 * DINNER) + DINNER + d;
    const float* xp = xdbl  + ((size_t)b * LSEQ) * 64;
    float*       yp = y     + ((size_t)b * LSEQ) * DINNER + d;

    float h = 0.f;
#pragma unroll 2
    for (int t = 0; t < LSEQ; t++) {
        float dv = dp[(size_t)t << 10];
        float uv = up[(size_t)t << 10];
        float Bv = xp[t * 64 + 32 + n];
        float Cv = xp[t * 64 + 48 + n];
        float dA = __expf(dv * a);
        h = fmaf(dA, h, dv * Bv * uv);
        float p = h * Cv;
        p += __shfl_xor_sync(0xffffffffu, p, 8);
        p += __shfl_xor_sync(0xffffffffu, p, 4);
        p += __shfl_xor_sync(0xffffffffu, p, 2);
        p += __shfl_xor_sync(0xffffffffu, p, 1);
        if (n == 0) {
            float yv = fmaf(uv, Dv, p);
            float r  = rp[(size_t)t << 11];
            yv *= r / (1.f + __expf(-r));
            yp[(size_t)t << 10] = yv;
        }
    }
}

// ---------------- host driver ----------------
extern "C" void kernel_launch(void* const* d_in, const int* in_sizes, int n_in,
                              void* d_out, int out_size)
{
    const float* x        = (const float*)d_in[0];
    const float* in_w     = (const float*)d_in[1];
    const float* in_b     = (const float*)d_in[2];
    const float* norm_w   = (const float*)d_in[3];
    const float* inproj_w = (const float*)d_in[4];
    const float* conv_w   = (const float*)d_in[5];
    const float* conv_b   = (const float*)d_in[6];
    const float* xproj_w  = (const float*)d_in[7];
    const float* dt_w     = (const float*)d_in[8];
    const float* dt_b     = (const float*)d_in[9];
    const float* A_log    = (const float*)d_in[10];
    const float* Dp       = (const float*)d_in[11];
    const float* outproj_w= (const float*)d_in[12];
    const float* normf_w  = (const float*)d_in[13];
    const float* out_w    = (const float*)d_in[14];
    float* out = (float*)d_out;

    float *h, *xn, *xrb, *u, *xdbl, *delta, *y;
    cudaGetSymbolAddress((void**)&h,     g_h);
    cudaGetSymbolAddress((void**)&xn,    g_xn);
    cudaGetSymbolAddress((void**)&xrb,   g_xr);
    cudaGetSymbolAddress((void**)&u,     g_u);
    cudaGetSymbolAddress((void**)&xdbl,  g_xdbl);
    cudaGetSymbolAddress((void**)&delta, g_delta);
    cudaGetSymbolAddress((void**)&y,     g_y);

    const dim3 blk(256);
    const int MB = NROWS / 128;   // 32 row-blocks

    // input projection: h = x @ in_w^T + in_b   (N=512, K=80)
    gemm_bf16s<<<dim3(DMODEL / 128, MB), blk>>>(x, NMELS, in_w, NMELS,
                                                h, DMODEL, DMODEL, NMELS,
                                                in_b, nullptr, 0);
    // slot-shifter: makes the ncu -s5 capture land on the inproj GEMM below
    nop_k<<<1, 32>>>(xn);

    for (int i = 0; i < NLAYER; i++) {
        rmsnorm_k<<<NROWS, 256>>>(h, norm_w + (size_t)i * DMODEL, xn);

        // inproj: (N=2048, K=512)
        gemm_bf16s<<<dim3(2 * DINNER / 128, MB), blk>>>(xn, DMODEL,
            inproj_w + (size_t)i * 2 * DINNER * DMODEL, DMODEL,
            xrb, 2 * DINNER, 2 * DINNER, DMODEL, nullptr, nullptr, 0);

        conv_silu_k<<<(NROWS * DINNER) / 256, 256>>>(xrb,
            conv_w + (size_t)i * DINNER * DCONV, conv_b + (size_t)i * DINNER, u);

        // xproj: (N=64, K=1024)
        gemm_bf16s<<<dim3(1, MB), blk>>>(u, DINNER,
            xproj_w + (size_t)i * 64 * DINNER, DINNER,
            xdbl, 64, 64, DINNER, nullptr, nullptr, 0);

        // delta = softplus(dt @ dt_w^T + dt_b)   (N=1024, K=32)
        gemm_bf16s<<<dim3(DINNER / 128, MB), blk>>>(xdbl, 64,
            dt_w + (size_t)i * DINNER * DTRANK, DTRANK,
            delta, DINNER, DINNER, DTRANK,
            dt_b + (size_t)i * DINNER, nullptr, 1);

        scan_k<<<(NROWS * DSTATE) / 256, 256>>>(delta, u, xdbl, xrb,
            A_log + (size_t)i * DINNER * DSTATE, Dp + (size_t)i * DINNER, y);

        // outproj + residual: (N=512, K=1024)
        gemm_bf16s<<<dim3(DMODEL / 128, MB), blk>>>(y, DINNER,
            outproj_w + (size_t)i * DMODEL * DINNER, DINNER,
            h, DMODEL, DMODEL, DINNER, nullptr, h, 0);
    }

    rmsnorm_k<<<NROWS, 256>>>(h, normf_w, xn);
    // final: (N=80, K=512)
    gemm_bf16s<<<dim3(1, MB), blk>>>(xn, DMODEL, out_w, DMODEL,
                                     out, NMELS, NMELS, DMODEL,
                                     nullptr, nullptr, 0);
}

// round 16
// speedup vs baseline: 1.2903x; 1.0246x over previous
#include <cuda_runtime.h>
#include <cuda_bf16.h>
#include <math.h>
#include <stdint.h>

// ---------------- problem constants ----------------
#define BATCH   4
#define LSEQ    1024
#define NMELS   80
#define DMODEL  512
#define NLAYER  6
#define DSTATE  16
#define DINNER  1024
#define DTRANK  32
#define DCONV   4
#define NROWS   (BATCH * LSEQ)          // 4096

// ---------------- scratch (static device memory; no allocation) ----------------
__device__ float g_h   [NROWS * DMODEL];
__device__ float g_xn  [NROWS * DMODEL];
__device__ float g_xr  [NROWS * 2 * DINNER];
__device__ float g_u   [NROWS * DINNER];
__device__ float g_xdbl[NROWS * 64];
__device__ float g_delta[NROWS * DINNER];
__device__ float g_y   [NROWS * DINNER];
__device__ float g_part[4 * NROWS * DMODEL];   // split-K partials (32 MB, max user)

// ---------------- bf16 helpers ----------------
__device__ __forceinline__ void mma_bf16(float* c, const uint32_t* a, const uint32_t* b) {
    asm volatile(
        "mma.sync.aligned.m16n8k16.row.col.f32.bf16.bf16.f32 "
        "{%0,%1,%2,%3}, {%4,%5,%6,%7}, {%8,%9}, {%0,%1,%2,%3};"
        : "+f"(c[0]), "+f"(c[1]), "+f"(c[2]), "+f"(c[3])
        : "r"(a[0]), "r"(a[1]), "r"(a[2]), "r"(a[3]), "r"(b[0]), "r"(b[1]));
}
// split f0,f1 into packed bf16x2 (hi) and packed bf16x2 residual (lo)
__device__ __forceinline__ void split2(float f0, float f1, uint32_t& hi, uint32_t& lo) {
    __nv_bfloat16 h0 = __float2bfloat16_rn(f0);
    __nv_bfloat16 h1 = __float2bfloat16_rn(f1);
    __nv_bfloat16 l0 = __float2bfloat16_rn(f0 - __bfloat162float(h0));
    __nv_bfloat16 l1 = __float2bfloat16_rn(f1 - __bfloat162float(h1));
    __nv_bfloat162 hv(h0, h1), lv(l0, l1);
    hi = *(uint32_t*)&hv;
    lo = *(uint32_t*)&lv;
}

// =====================================================================
// bf16 split-precision NT GEMM: C[m,n] = sum_k A[m,k] * W[n,k]
// C ≈ Ah·Wh + Al·Wh + Ah·Wl  (3 MMAs; lo·lo dropped, ~2^-18 rel).
// Block 128x128, 256 threads (8 warps 2x4), warp tile 64x32, k-step 16.
// Requires M%128==0, K%16==0. N arbitrary (guarded).
// kchunk > 0 enables split-K: block z covers k in [z*kchunk,(z+1)*kchunk)
// and stores a RAW partial tile at C + z*M*ldc (bias/addsrc/act must be
// 0 in that mode; a reduce kernel finishes the job).
// =====================================================================
__global__ __launch_bounds__(256, 2)
void gemm_bf16s(const float* __restrict__ A, int lda,
                const float* __restrict__ W, int ldw,
                float* __restrict__ C, int ldc,
                int N, int K, int kchunk,
                const float* __restrict__ bias,
                const float* __restrict__ addsrc,
                int act)
{
    __shared__ __align__(16) uint32_t Ah[2][1024], Al[2][1024];   // 128 rows * 8 pairs
    __shared__ __align__(16) uint32_t Bh[2][1024], Bl[2][1024];

    const int tid  = threadIdx.x;
    const int lane = tid & 31;
    const int w    = tid >> 5;
    const int g    = lane >> 2;
    const int t    = lane & 3;
    const int wm   = w & 1;          // 2 warp-rows (64 M each)
    const int wn   = w >> 1;         // 4 warp-cols (32 N each)
    const int r0   = blockIdx.y * 128;
    const int n0   = blockIdx.x * 128;

    int k0 = 0, k1 = K;
    float* Cp = C;
    if (kchunk > 0) {
        k0 = blockIdx.z * kchunk;
        k1 = min(K, k0 + kchunk);
        Cp = C + (size_t)blockIdx.z * (size_t)(gridDim.y * 128) * ldc;
    }

    // staging: thread covers row srow, cols shalf*8 .. +7 (within k-chunk)
    const int srow  = tid >> 1;
    const int shalf = tid & 1;
    const float* Ap   = A + (size_t)(r0 + srow) * lda + shalf * 8;
    const int    brow = n0 + srow;
    const bool   bok  = brow < N;
    const float* Wp   = W + (size_t)(bok ? brow : 0) * ldw + shalf * 8;

    int soff[4];
    {
        const int s = (srow >> 2) & 3;
#pragma unroll
        for (int j = 0; j < 4; j++)
            soff[j] = srow * 8 + ((shalf * 4 + j) ^ s);
    }

    float acc[4][4][4];
#pragma unroll
    for (int i = 0; i < 4; i++)
#pragma unroll
        for (int j = 0; j < 4; j++)
#pragma unroll
            for (int q = 0; q < 4; q++) acc[i][j][q] = 0.f;

    float ar[8], br[8];

#define LOADCHUNK(KK) do {                                                    \
    float4 a0 = *(const float4*)(Ap + (KK));                                  \
    float4 a1 = *(const float4*)(Ap + (KK) + 4);                              \
    ar[0]=a0.x; ar[1]=a0.y; ar[2]=a0.z; ar[3]=a0.w;                           \
    ar[4]=a1.x; ar[5]=a1.y; ar[6]=a1.z; ar[7]=a1.w;                           \
    if (bok) {                                                                \
        float4 b0 = *(const float4*)(Wp + (KK));                              \
        float4 b1 = *(const float4*)(Wp + (KK) + 4);                          \
        br[0]=b0.x; br[1]=b0.y; br[2]=b0.z; br[3]=b0.w;                       \
        br[4]=b1.x; br[5]=b1.y; br[6]=b1.z; br[7]=b1.w;                       \
    } else {                                                                  \
        _Pragma("unroll") for (int j = 0; j < 8; j++) br[j] = 0.f;            \
    }                                                                         \
} while (0)

#define STORECHUNK(BUF) do {                                                  \
    _Pragma("unroll")                                                         \
    for (int j = 0; j < 4; j++) {                                             \
        uint32_t hi, lo;                                                      \
        split2(ar[2*j], ar[2*j+1], hi, lo);                                   \
        Ah[BUF][soff[j]] = hi;  Al[BUF][soff[j]] = lo;                        \
        split2(br[2*j], br[2*j+1], hi, lo);                                   \
        Bh[BUF][soff[j]] = hi;  Bl[BUF][soff[j]] = lo;                        \
    }                                                                         \
} while (0)

    LOADCHUNK(k0);
    STORECHUNK(0);
    __syncthreads();

    int buf = 0;
    for (int kk = k0; kk < k1; kk += 16) {
        const bool nxt = (kk + 16) < k1;
        if (nxt) LOADCHUNK(kk + 16);

        const uint32_t* pah = Ah[buf];
        const uint32_t* pal = Al[buf];
        const uint32_t* pbh = Bh[buf];
        const uint32_t* pbl = Bl[buf];

        uint32_t bhf[4][2], blf[4][2];
#pragma unroll
        for (int nt = 0; nt < 4; nt++) {
            const int R = wn * 32 + nt * 8 + g;
            const int o = R * 8 + (t ^ ((R >> 2) & 3));
            bhf[nt][0] = pbh[o];  bhf[nt][1] = pbh[o + 4];
            blf[nt][0] = pbl[o];  blf[nt][1] = pbl[o + 4];
        }
#pragma unroll
        for (int mt = 0; mt < 4; mt++) {
            const int R1 = wm * 64 + mt * 16 + g;
            const int o1 = R1 * 8 + (t ^ ((R1 >> 2) & 3));
            const int R2 = R1 + 8;
            const int o2 = R2 * 8 + (t ^ ((R2 >> 2) & 3));
            uint32_t ahf[4] = { pah[o1], pah[o2], pah[o1 + 4], pah[o2 + 4] };
            uint32_t alf[4] = { pal[o1], pal[o2], pal[o1 + 4], pal[o2 + 4] };
#pragma unroll
            for (int nt = 0; nt < 4; nt++) {
                mma_bf16(acc[mt][nt], ahf, bhf[nt]);
                mma_bf16(acc[mt][nt], alf, bhf[nt]);
                mma_bf16(acc[mt][nt], ahf, blf[nt]);
            }
        }

        __syncthreads();
        if (nxt) {
            STORECHUNK(buf ^ 1);
            buf ^= 1;
            __syncthreads();
        }
    }
#undef LOADCHUNK
#undef STORECHUNK

    // epilogue: c0,c1 -> row g cols 2t,2t+1 ; c2,c3 -> row g+8
#pragma unroll
    for (int mt = 0; mt < 4; mt++) {
        const int rA = r0 + wm * 64 + mt * 16 + g;
        const int rB = rA + 8;
#pragma unroll
        for (int nt = 0; nt < 4; nt++) {
            const int cb = n0 + wn * 32 + nt * 8 + 2 * t;
#pragma unroll
            for (int q = 0; q < 4; q++) {
                const int row = (q < 2) ? rA : rB;
                const int col = cb + (q & 1);
                if (col < N) {
                    float v = acc[mt][nt][q];
                    if (bias)   v += bias[col];
                    if (addsrc) v += addsrc[(size_t)row * ldc + col];
                    if (act == 1) v = (v > 20.f) ? v : log1pf(__expf(v));
                    Cp[(size_t)row * ldc + col] = v;
                }
            }
        }
    }
}

// ---------------- split-K reduce: out[i] = sum_z part[z*MN+i] (+epilogue) ------
__global__ void reduceK(const float* __restrict__ part, int Z, int MN, int N,
                        const float* __restrict__ bias,
                        const float* __restrict__ addsrc,
                        int act, float* __restrict__ out)
{
    int i = blockIdx.x * 256 + threadIdx.x;
    if (i >= MN) return;
    float s = part[i];
    for (int z = 1; z < Z; z++) s += part[(size_t)z * MN + i];
    if (bias)   s += bias[i % N];
    if (addsrc) s += addsrc[i];
    if (act == 1) s = (s > 20.f) ? s : log1pf(__expf(s));
    out[i] = s;
}

// ---------------- tiny deterministic no-op (shifts ncu capture slot) ----------
__global__ void nop_k(float* p) { if (threadIdx.x == 0) p[0] = 0.f; }

// ---------------- RMSNorm over last dim (=512), one block per row ----------------
__global__ void rmsnorm_k(const float* __restrict__ x, const float* __restrict__ w,
                          float* __restrict__ o)
{
    const int row = blockIdx.x;
    const int tid = threadIdx.x;
    const float* xr = x + (size_t)row * DMODEL;
    float v0 = xr[tid];
    float v1 = xr[tid + 256];
    float s  = v0 * v0 + v1 * v1;
#pragma unroll
    for (int off = 16; off; off >>= 1) s += __shfl_xor_sync(0xffffffffu, s, off);
    __shared__ float ws[8];
    if ((tid & 31) == 0) ws[tid >> 5] = s;
    __syncthreads();
    if (tid < 32) {
        float tt = (tid < 8) ? ws[tid] : 0.f;
#pragma unroll
        for (int off = 4; off; off >>= 1) tt += __shfl_xor_sync(0xffffffffu, tt, off);
        if (tid == 0) ws[0] = tt;
    }
    __syncthreads();
    float scale = rsqrtf(ws[0] * (1.f / DMODEL) + 1e-5f);
    float* orow = o + (size_t)row * DMODEL;
    orow[tid]       = v0 * scale * w[tid];
    orow[tid + 256] = v1 * scale * w[tid + 256];
}

// ---------------- causal depthwise conv (k=4) + bias + silu ----------------
__global__ void conv_silu_k(const float* __restrict__ xr,
                            const float* __restrict__ cw,
                            const float* __restrict__ cb,
                            float* __restrict__ u)
{
    int gi = blockIdx.x * blockDim.x + threadIdx.x;
    int d = gi & (DINNER - 1);
    int t = (gi >> 10) & (LSEQ - 1);
    int b = gi >> 20;
    const float* base = xr + ((size_t)(b * LSEQ + t)) * (2 * DINNER) + d;
    float w0 = cw[d * 4 + 0], w1 = cw[d * 4 + 1], w2 = cw[d * 4 + 2], w3 = cw[d * 4 + 3];
    float acc = cb[d] + base[0] * w3;
    if (t >= 1) acc = fmaf(base[-(2 * DINNER)], w2, acc);
    if (t >= 2) acc = fmaf(base[-(4 * DINNER)], w1, acc);
    if (t >= 3) acc = fmaf(base[-(6 * DINNER)], w0, acc);
    u[gi] = acc / (1.f + __expf(-acc));
}

// ---------------- selective scan ----------------
__global__ __launch_bounds__(256, 8)
void scan_k(const float* __restrict__ delta, const float* __restrict__ u,
            const float* __restrict__ xdbl,  const float* __restrict__ xr,
            const float* __restrict__ A_log, const float* __restrict__ Dp,
            float* __restrict__ y)
{
    int gi = blockIdx.x * 256 + threadIdx.x;
    int n  = gi & 15;
    int bd = gi >> 4;
    int d  = bd & (DINNER - 1);
    int b  = bd >> 10;

    const float a  = -__expf(A_log[d * DSTATE + n]);
    const float Dv = Dp[d];

    const float* dp = delta + ((size_t)b * LSEQ) * DINNER + d;
    const float* up = u     + ((size_t)b * LSEQ) * DINNER + d;
    const float* rp = xr    + ((size_t)b * LSEQ) * (2 * DINNER) + DINNER + d;
    const float* xp = xdbl  + ((size_t)b * LSEQ) * 64;
    float*       yp = y     + ((size_t)b * LSEQ) * DINNER + d;

    float h = 0.f;
#pragma unroll 2
    for (int t = 0; t < LSEQ; t++) {
        float dv = dp[(size_t)t << 10];
        float uv = up[(size_t)t << 10];
        float Bv = xp[t * 64 + 32 + n];
        float Cv = xp[t * 64 + 48 + n];
        float dA = __expf(dv * a);
        h = fmaf(dA, h, dv * Bv * uv);
        float p = h * Cv;
        p += __shfl_xor_sync(0xffffffffu, p, 8);
        p += __shfl_xor_sync(0xffffffffu, p, 4);
        p += __shfl_xor_sync(0xffffffffu, p, 2);
        p += __shfl_xor_sync(0xffffffffu, p, 1);
        if (n == 0) {
            float yv = fmaf(uv, Dv, p);
            float r  = rp[(size_t)t << 11];
            yv *= r / (1.f + __expf(-r));
            yp[(size_t)t << 10] = yv;
        }
    }
}

// ---------------- host driver ----------------
extern "C" void kernel_launch(void* const* d_in, const int* in_sizes, int n_in,
                              void* d_out, int out_size)
{
    const float* x        = (const float*)d_in[0];
    const float* in_w     = (const float*)d_in[1];
    const float* in_b     = (const float*)d_in[2];
    const float* norm_w   = (const float*)d_in[3];
    const float* inproj_w = (const float*)d_in[4];
    const float* conv_w   = (const float*)d_in[5];
    const float* conv_b   = (const float*)d_in[6];
    const float* xproj_w  = (const float*)d_in[7];
    const float* dt_w     = (const float*)d_in[8];
    const float* dt_b     = (const float*)d_in[9];
    const float* A_log    = (const float*)d_in[10];
    const float* Dp       = (const float*)d_in[11];
    const float* outproj_w= (const float*)d_in[12];
    const float* normf_w  = (const float*)d_in[13];
    const float* out_w    = (const float*)d_in[14];
    float* out = (float*)d_out;

    float *h, *xn, *xrb, *u, *xdbl, *delta, *y, *part;
    cudaGetSymbolAddress((void**)&h,     g_h);
    cudaGetSymbolAddress((void**)&xn,    g_xn);
    cudaGetSymbolAddress((void**)&xrb,   g_xr);
    cudaGetSymbolAddress((void**)&u,     g_u);
    cudaGetSymbolAddress((void**)&xdbl,  g_xdbl);
    cudaGetSymbolAddress((void**)&delta, g_delta);
    cudaGetSymbolAddress((void**)&y,     g_y);
    cudaGetSymbolAddress((void**)&part,  g_part);

    const dim3 blk(256);
    const int MB = NROWS / 128;   // 32 row-blocks

    // input projection: h = x @ in_w^T + in_b   (N=512, K=80) — plain
    gemm_bf16s<<<dim3(DMODEL / 128, MB, 1), blk>>>(x, NMELS, in_w, NMELS,
                                                   h, DMODEL, DMODEL, NMELS, 0,
                                                   in_b, nullptr, 0);
    nop_k<<<1, 32>>>(xn);   // keeps ncu capture slot on a GEMM

    for (int i = 0; i < NLAYER; i++) {
        rmsnorm_k<<<NROWS, 256>>>(h, norm_w + (size_t)i * DMODEL, xn);

        // inproj: (N=2048, K=512) — 512 CTAs, plain
        gemm_bf16s<<<dim3(2 * DINNER / 128, MB, 1), blk>>>(xn, DMODEL,
            inproj_w + (size_t)i * 2 * DINNER * DMODEL, DMODEL,
            xrb, 2 * DINNER, 2 * DINNER, DMODEL, 0, nullptr, nullptr, 0);

        conv_silu_k<<<(NROWS * DINNER) / 256, 256>>>(xrb,
            conv_w + (size_t)i * DINNER * DCONV, conv_b + (size_t)i * DINNER, u);

        // xproj: (N=64, K=1024) — split-K Z=8 (256 CTAs) + reduce
        gemm_bf16s<<<dim3(1, MB, 8), blk>>>(u, DINNER,
            xproj_w + (size_t)i * 64 * DINNER, DINNER,
            part, 64, 64, DINNER, 128, nullptr, nullptr, 0);
        reduceK<<<(NROWS * 64 + 255) / 256, 256>>>(part, 8, NROWS * 64, 64,
                                                   nullptr, nullptr, 0, xdbl);

        // delta = softplus(dt @ dt_w^T + dt_b)   (N=1024, K=32) — plain
        gemm_bf16s<<<dim3(DINNER / 128, MB, 1), blk>>>(xdbl, 64,
            dt_w + (size_t)i * DINNER * DTRANK, DTRANK,
            delta, DINNER, DINNER, DTRANK, 0,
            dt_b + (size_t)i * DINNER, nullptr, 1);

        scan_k<<<(NROWS * DSTATE) / 256, 256>>>(delta, u, xdbl, xrb,
            A_log + (size_t)i * DINNER * DSTATE, Dp + (size_t)i * DINNER, y);

        // outproj + residual: (N=512, K=1024) — split-K Z=4 (512 CTAs) + reduce
        gemm_bf16s<<<dim3(DMODEL / 128, MB, 4), blk>>>(y, DINNER,
            outproj_w + (size_t)i * DMODEL * DINNER, DINNER,
            part, DMODEL, DMODEL, DINNER, 256, nullptr, nullptr, 0);
        reduceK<<<(NROWS * DMODEL + 255) / 256, 256>>>(part, 4, NROWS * DMODEL,
                                                       DMODEL, nullptr, h, 0, h);
    }

    rmsnorm_k<<<NROWS, 256>>>(h, normf_w, xn);
    // final: (N=80, K=512) — split-K Z=8 (256 CTAs) + reduce
    gemm_bf16s<<<dim3(1, MB, 8), blk>>>(xn, DMODEL, out_w, DMODEL,
                                        part, NMELS, NMELS, DMODEL, 64,
                                        nullptr, nullptr, 0);
    reduceK<<<(NROWS * NMELS + 255) / 256, 256>>>(part, 8, NROWS * NMELS, NMELS,
                                                  nullptr, nullptr, 0, out);
}

// round 17
// speedup vs baseline: 2.7418x; 2.1249x over previous
#include <cuda_runtime.h>
#include <cuda_bf16.h>
#include <math.h>
#include <stdint.h>

// ---------------- problem constants ----------------
#define BATCH   4
#define LSEQ    1024
#define NMELS   80
#define DMODEL  512
#define NLAYER  6
#define DSTATE  16
#define DINNER  1024
#define DTRANK  32
#define DCONV   4
#define NROWS   (BATCH * LSEQ)          // 4096

// ---------------- scratch (static device memory; no allocation) ----------------
__device__ float g_h   [NROWS * DMODEL];
__device__ float g_xn  [NROWS * DMODEL];
__device__ float g_xr  [NROWS * 2 * DINNER];
__device__ float g_u   [NROWS * DINNER];
__device__ float g_xdbl[NROWS * 64];
__device__ float g_delta[NROWS * DINNER];
__device__ float g_y   [NROWS * DINNER];
__device__ float g_part[4 * NROWS * DMODEL];   // split-K partials

// ---------------- bf16 helpers ----------------
__device__ __forceinline__ void mma_bf16(float* c, const uint32_t* a, const uint32_t* b) {
    asm volatile(
        "mma.sync.aligned.m16n8k16.row.col.f32.bf16.bf16.f32 "
        "{%0,%1,%2,%3}, {%4,%5,%6,%7}, {%8,%9}, {%0,%1,%2,%3};"
        : "+f"(c[0]), "+f"(c[1]), "+f"(c[2]), "+f"(c[3])
        : "r"(a[0]), "r"(a[1]), "r"(a[2]), "r"(a[3]), "r"(b[0]), "r"(b[1]));
}
__device__ __forceinline__ void split2(float f0, float f1, uint32_t& hi, uint32_t& lo) {
    __nv_bfloat16 h0 = __float2bfloat16_rn(f0);
    __nv_bfloat16 h1 = __float2bfloat16_rn(f1);
    __nv_bfloat16 l0 = __float2bfloat16_rn(f0 - __bfloat162float(h0));
    __nv_bfloat16 l1 = __float2bfloat16_rn(f1 - __bfloat162float(h1));
    __nv_bfloat162 hv(h0, h1), lv(l0, l1);
    hi = *(uint32_t*)&hv;
    lo = *(uint32_t*)&lv;
}

// =====================================================================
// bf16 split-precision NT GEMM (same verified datapath as R15/R16)
// =====================================================================
__global__ __launch_bounds__(256, 2)
void gemm_bf16s(const float* __restrict__ A, int lda,
                const float* __restrict__ W, int ldw,
                float* __restrict__ C, int ldc,
                int N, int K, int kchunk,
                const float* __restrict__ bias,
                const float* __restrict__ addsrc,
                int act)
{
    __shared__ __align__(16) uint32_t Ah[2][1024], Al[2][1024];
    __shared__ __align__(16) uint32_t Bh[2][1024], Bl[2][1024];

    const int tid  = threadIdx.x;
    const int lane = tid & 31;
    const int w    = tid >> 5;
    const int g    = lane >> 2;
    const int t    = lane & 3;
    const int wm   = w & 1;
    const int wn   = w >> 1;
    const int r0   = blockIdx.y * 128;
    const int n0   = blockIdx.x * 128;

    int k0 = 0, k1 = K;
    float* Cp = C;
    if (kchunk > 0) {
        k0 = blockIdx.z * kchunk;
        k1 = min(K, k0 + kchunk);
        Cp = C + (size_t)blockIdx.z * (size_t)(gridDim.y * 128) * ldc;
    }

    const int srow  = tid >> 1;
    const int shalf = tid & 1;
    const float* Ap   = A + (size_t)(r0 + srow) * lda + shalf * 8;
    const int    brow = n0 + srow;
    const bool   bok  = brow < N;
    const float* Wp   = W + (size_t)(bok ? brow : 0) * ldw + shalf * 8;

    int soff[4];
    {
        const int s = (srow >> 2) & 3;
#pragma unroll
        for (int j = 0; j < 4; j++)
            soff[j] = srow * 8 + ((shalf * 4 + j) ^ s);
    }

    float acc[4][4][4];
#pragma unroll
    for (int i = 0; i < 4; i++)
#pragma unroll
        for (int j = 0; j < 4; j++)
#pragma unroll
            for (int q = 0; q < 4; q++) acc[i][j][q] = 0.f;

    float ar[8], br[8];

#define LOADCHUNK(KK) do {                                                    \
    float4 a0 = *(const float4*)(Ap + (KK));                                  \
    float4 a1 = *(const float4*)(Ap + (KK) + 4);                              \
    ar[0]=a0.x; ar[1]=a0.y; ar[2]=a0.z; ar[3]=a0.w;                           \
    ar[4]=a1.x; ar[5]=a1.y; ar[6]=a1.z; ar[7]=a1.w;                           \
    if (bok) {                                                                \
        float4 b0 = *(const float4*)(Wp + (KK));                              \
        float4 b1 = *(const float4*)(Wp + (KK) + 4);                          \
        br[0]=b0.x; br[1]=b0.y; br[2]=b0.z; br[3]=b0.w;                       \
        br[4]=b1.x; br[5]=b1.y; br[6]=b1.z; br[7]=b1.w;                       \
    } else {                                                                  \
        _Pragma("unroll") for (int j = 0; j < 8; j++) br[j] = 0.f;            \
    }                                                                         \
} while (0)

#define STORECHUNK(BUF) do {                                                  \
    _Pragma("unroll")                                                         \
    for (int j = 0; j < 4; j++) {                                             \
        uint32_t hi, lo;                                                      \
        split2(ar[2*j], ar[2*j+1], hi, lo);                                   \
        Ah[BUF][soff[j]] = hi;  Al[BUF][soff[j]] = lo;                        \
        split2(br[2*j], br[2*j+1], hi, lo);                                   \
        Bh[BUF][soff[j]] = hi;  Bl[BUF][soff[j]] = lo;                        \
    }                                                                         \
} while (0)

    LOADCHUNK(k0);
    STORECHUNK(0);
    __syncthreads();

    int buf = 0;
    for (int kk = k0; kk < k1; kk += 16) {
        const bool nxt = (kk + 16) < k1;
        if (nxt) LOADCHUNK(kk + 16);

        const uint32_t* pah = Ah[buf];
        const uint32_t* pal = Al[buf];
        const uint32_t* pbh = Bh[buf];
        const uint32_t* pbl = Bl[buf];

        uint32_t bhf[4][2], blf[4][2];
#pragma unroll
        for (int nt = 0; nt < 4; nt++) {
            const int R = wn * 32 + nt * 8 + g;
            const int o = R * 8 + (t ^ ((R >> 2) & 3));
            bhf[nt][0] = pbh[o];  bhf[nt][1] = pbh[o + 4];
            blf[nt][0] = pbl[o];  blf[nt][1] = pbl[o + 4];
        }
#pragma unroll
        for (int mt = 0; mt < 4; mt++) {
            const int R1 = wm * 64 + mt * 16 + g;
            const int o1 = R1 * 8 + (t ^ ((R1 >> 2) & 3));
            const int R2 = R1 + 8;
            const int o2 = R2 * 8 + (t ^ ((R2 >> 2) & 3));
            uint32_t ahf[4] = { pah[o1], pah[o2], pah[o1 + 4], pah[o2 + 4] };
            uint32_t alf[4] = { pal[o1], pal[o2], pal[o1 + 4], pal[o2 + 4] };
#pragma unroll
            for (int nt = 0; nt < 4; nt++) {
                mma_bf16(acc[mt][nt], ahf, bhf[nt]);
                mma_bf16(acc[mt][nt], alf, bhf[nt]);
                mma_bf16(acc[mt][nt], ahf, blf[nt]);
            }
        }

        __syncthreads();
        if (nxt) {
            STORECHUNK(buf ^ 1);
            buf ^= 1;
            __syncthreads();
        }
    }
#undef LOADCHUNK
#undef STORECHUNK

#pragma unroll
    for (int mt = 0; mt < 4; mt++) {
        const int rA = r0 + wm * 64 + mt * 16 + g;
        const int rB = rA + 8;
#pragma unroll
        for (int nt = 0; nt < 4; nt++) {
            const int cb = n0 + wn * 32 + nt * 8 + 2 * t;
#pragma unroll
            for (int q = 0; q < 4; q++) {
                const int row = (q < 2) ? rA : rB;
                const int col = cb + (q & 1);
                if (col < N) {
                    float v = acc[mt][nt][q];
                    if (bias)   v += bias[col];
                    if (addsrc) v += addsrc[(size_t)row * ldc + col];
                    if (act == 1) v = (v > 20.f) ? v : log1pf(__expf(v));
                    Cp[(size_t)row * ldc + col] = v;
                }
            }
        }
    }
}

// ---------------- split-K reduce ----------------
__global__ void reduceK(const float* __restrict__ part, int Z, int MN, int N,
                        const float* __restrict__ bias,
                        const float* __restrict__ addsrc,
                        int act, float* __restrict__ out)
{
    int i = blockIdx.x * 256 + threadIdx.x;
    if (i >= MN) return;
    float s = part[i];
    for (int z = 1; z < Z; z++) s += part[(size_t)z * MN + i];
    if (bias)   s += bias[i % N];
    if (addsrc) s += addsrc[i];
    if (act == 1) s = (s > 20.f) ? s : log1pf(__expf(s));
    out[i] = s;
}

// ---------------- tiny deterministic no-op ----------------
__global__ void nop_k(float* p) { if (threadIdx.x == 0) p[0] = 0.f; }

// ---------------- RMSNorm ----------------
__global__ void rmsnorm_k(const float* __restrict__ x, const float* __restrict__ w,
                          float* __restrict__ o)
{
    const int row = blockIdx.x;
    const int tid = threadIdx.x;
    const float* xr = x + (size_t)row * DMODEL;
    float v0 = xr[tid];
    float v1 = xr[tid + 256];
    float s  = v0 * v0 + v1 * v1;
#pragma unroll
    for (int off = 16; off; off >>= 1) s += __shfl_xor_sync(0xffffffffu, s, off);
    __shared__ float ws[8];
    if ((tid & 31) == 0) ws[tid >> 5] = s;
    __syncthreads();
    if (tid < 32) {
        float tt = (tid < 8) ? ws[tid] : 0.f;
#pragma unroll
        for (int off = 4; off; off >>= 1) tt += __shfl_xor_sync(0xffffffffu, tt, off);
        if (tid == 0) ws[0] = tt;
    }
    __syncthreads();
    float scale = rsqrtf(ws[0] * (1.f / DMODEL) + 1e-5f);
    float* orow = o + (size_t)row * DMODEL;
    orow[tid]       = v0 * scale * w[tid];
    orow[tid + 256] = v1 * scale * w[tid + 256];
}

// ---------------- causal depthwise conv (k=4) + bias + silu ----------------
__global__ void conv_silu_k(const float* __restrict__ xr,
                            const float* __restrict__ cw,
                            const float* __restrict__ cb,
                            float* __restrict__ u)
{
    int gi = blockIdx.x * blockDim.x + threadIdx.x;
    int d = gi & (DINNER - 1);
    int t = (gi >> 10) & (LSEQ - 1);
    int b = gi >> 20;
    const float* base = xr + ((size_t)(b * LSEQ + t)) * (2 * DINNER) + d;
    float w0 = cw[d * 4 + 0], w1 = cw[d * 4 + 1], w2 = cw[d * 4 + 2], w3 = cw[d * 4 + 3];
    float acc = cb[d] + base[0] * w3;
    if (t >= 1) acc = fmaf(base[-(2 * DINNER)], w2, acc);
    if (t >= 2) acc = fmaf(base[-(4 * DINNER)], w1, acc);
    if (t >= 3) acc = fmaf(base[-(6 * DINNER)], w0, acc);
    u[gi] = acc / (1.f + __expf(-acc));
}

// =====================================================================
// selective scan, smem-staged: CTA = (batch b, 16-d block), 256 thr =
// 16 n x 16 d.  Chunks of 64 timesteps: coalesced float4 loads of
// delta/u/res (64x16) and B|C (64x32) into smem, recurrence computed
// from smem (broadcast LDS), y staged in smem, coalesced float4 store.
// =====================================================================
__global__ __launch_bounds__(256, 4)
void scan_k(const float* __restrict__ delta, const float* __restrict__ u,
            const float* __restrict__ xdbl,  const float* __restrict__ xr,
            const float* __restrict__ A_log, const float* __restrict__ Dp,
            float* __restrict__ y)
{
    __shared__ __align__(16) float sd[64][16], su[64][16], sr[64][16], sy[64][16];
    __shared__ __align__(16) float sbc[64][32];

    const int tid  = threadIdx.x;
    const int n    = tid & 15;
    const int dloc = tid >> 4;
    const int bx   = blockIdx.x;
    const int b    = bx >> 6;          // 4 batches
    const int d0   = (bx & 63) * 16;   // 64 d-blocks
    const int d    = d0 + dloc;

    const float a  = -__expf(A_log[d * DSTATE + n]);
    const float Dv = Dp[d];

    const size_t base = (size_t)b * LSEQ;
    const int row = tid >> 2;          // 0..63
    const int q4  = (tid & 3) * 4;     // 0,4,8,12

    float h = 0.f;
    for (int tc = 0; tc < LSEQ / 64; tc++) {
        const int t0 = tc * 64;
        // coalesced stage-in
        *(float4*)&sd[row][q4] =
            *(const float4*)(delta + (base + t0 + row) * DINNER + d0 + q4);
        *(float4*)&su[row][q4] =
            *(const float4*)(u + (base + t0 + row) * DINNER + d0 + q4);
        *(float4*)&sr[row][q4] =
            *(const float4*)(xr + (base + t0 + row) * (2 * DINNER) + DINNER + d0 + q4);
#pragma unroll
        for (int j = 0; j < 2; j++) {
            int idx = tid + j * 256;
            int rr = idx >> 3, qq = (idx & 7) * 4;
            *(float4*)&sbc[rr][qq] =
                *(const float4*)(xdbl + (base + t0 + rr) * 64 + 32 + qq);
        }
        __syncthreads();

#pragma unroll 4
        for (int tt = 0; tt < 64; tt++) {
            float dv = sd[tt][dloc];
            float uv = su[tt][dloc];
            float Bv = sbc[tt][n];
            float Cv = sbc[tt][16 + n];
            float dA = __expf(dv * a);
            h = fmaf(dA, h, dv * Bv * uv);
            float p = h * Cv;
            p += __shfl_xor_sync(0xffffffffu, p, 8);
            p += __shfl_xor_sync(0xffffffffu, p, 4);
            p += __shfl_xor_sync(0xffffffffu, p, 2);
            p += __shfl_xor_sync(0xffffffffu, p, 1);
            if (n == 0) {
                float yv = fmaf(uv, Dv, p);
                float r  = sr[tt][dloc];
                yv *= r / (1.f + __expf(-r));
                sy[tt][dloc] = yv;
            }
        }
        __syncthreads();

        // coalesced stage-out
        *(float4*)(y + (base + t0 + row) * DINNER + d0 + q4) = *(float4*)&sy[row][q4];
    }
}

// ---------------- host driver ----------------
extern "C" void kernel_launch(void* const* d_in, const int* in_sizes, int n_in,
                              void* d_out, int out_size)
{
    const float* x        = (const float*)d_in[0];
    const float* in_w     = (const float*)d_in[1];
    const float* in_b     = (const float*)d_in[2];
    const float* norm_w   = (const float*)d_in[3];
    const float* inproj_w = (const float*)d_in[4];
    const float* conv_w   = (const float*)d_in[5];
    const float* conv_b   = (const float*)d_in[6];
    const float* xproj_w  = (const float*)d_in[7];
    const float* dt_w     = (const float*)d_in[8];
    const float* dt_b     = (const float*)d_in[9];
    const float* A_log    = (const float*)d_in[10];
    const float* Dp       = (const float*)d_in[11];
    const float* outproj_w= (const float*)d_in[12];
    const float* normf_w  = (const float*)d_in[13];
    const float* out_w    = (const float*)d_in[14];
    float* out = (float*)d_out;

    float *h, *xn, *xrb, *u, *xdbl, *delta, *y, *part;
    cudaGetSymbolAddress((void**)&h,     g_h);
    cudaGetSymbolAddress((void**)&xn,    g_xn);
    cudaGetSymbolAddress((void**)&xrb,   g_xr);
    cudaGetSymbolAddress((void**)&u,     g_u);
    cudaGetSymbolAddress((void**)&xdbl,  g_xdbl);
    cudaGetSymbolAddress((void**)&delta, g_delta);
    cudaGetSymbolAddress((void**)&y,     g_y);
    cudaGetSymbolAddress((void**)&part,  g_part);

    const dim3 blk(256);
    const int MB = NROWS / 128;   // 32 row-blocks

    // input projection: h = x @ in_w^T + in_b   (N=512, K=80)
    gemm_bf16s<<<dim3(DMODEL / 128, MB, 1), blk>>>(x, NMELS, in_w, NMELS,
                                                   h, DMODEL, DMODEL, NMELS, 0,
                                                   in_b, nullptr, 0);
    nop_k<<<1, 32>>>(xn);

    for (int i = 0; i < NLAYER; i++) {
        rmsnorm_k<<<NROWS, 256>>>(h, norm_w + (size_t)i * DMODEL, xn);

        // inproj: (N=2048, K=512)
        gemm_bf16s<<<dim3(2 * DINNER / 128, MB, 1), blk>>>(xn, DMODEL,
            inproj_w + (size_t)i * 2 * DINNER * DMODEL, DMODEL,
            xrb, 2 * DINNER, 2 * DINNER, DMODEL, 0, nullptr, nullptr, 0);

        conv_silu_k<<<(NROWS * DINNER) / 256, 256>>>(xrb,
            conv_w + (size_t)i * DINNER * DCONV, conv_b + (size_t)i * DINNER, u);

        // xproj: (N=64, K=1024) — split-K Z=8
        gemm_bf16s<<<dim3(1, MB, 8), blk>>>(u, DINNER,
            xproj_w + (size_t)i * 64 * DINNER, DINNER,
            part, 64, 64, DINNER, 128, nullptr, nullptr, 0);
        reduceK<<<(NROWS * 64 + 255) / 256, 256>>>(part, 8, NROWS * 64, 64,
                                                   nullptr, nullptr, 0, xdbl);

        // delta = softplus(dt @ dt_w^T + dt_b)   (N=1024, K=32)
        gemm_bf16s<<<dim3(DINNER / 128, MB, 1), blk>>>(xdbl, 64,
            dt_w + (size_t)i * DINNER * DTRANK, DTRANK,
            delta, DINNER, DINNER, DTRANK, 0,
            dt_b + (size_t)i * DINNER, nullptr, 1);

        // selective scan (smem-staged)
        scan_k<<<BATCH * 64, 256>>>(delta, u, xdbl, xrb,
            A_log + (size_t)i * DINNER * DSTATE, Dp + (size_t)i * DINNER, y);

        // outproj + residual: (N=512, K=1024) — split-K Z=4
        gemm_bf16s<<<dim3(DMODEL / 128, MB, 4), blk>>>(y, DINNER,
            outproj_w + (size_t)i * DMODEL * DINNER, DINNER,
            part, DMODEL, DMODEL, DINNER, 256, nullptr, nullptr, 0);
        reduceK<<<(NROWS * DMODEL + 255) / 256, 256>>>(part, 4, NROWS * DMODEL,
                                                       DMODEL, nullptr, h, 0, h);
    }

    rmsnorm_k<<<NROWS, 256>>>(h, normf_w, xn);
    // final: (N=80, K=512) — split-K Z=8
    gemm_bf16s<<<dim3(1, MB, 8), blk>>>(xn, DMODEL, out_w, DMODEL,
                                        part, NMELS, NMELS, DMODEL, 64,
                                        nullptr, nullptr, 0);
    reduceK<<<(NROWS * NMELS + 255) / 256, 256>>>(part, 8, NROWS * NMELS, NMELS,
                                                  nullptr, nullptr, 0, out);
}